// round 16
// baseline (speedup 1.0000x reference)
#include <cuda_runtime.h>
#include <cuda_fp16.h>
#include <float.h>
#include <stdint.h>

#define N_NODES 50000
#define N_EDGES 800000
#define F 128
#define L_LAYERS 3
#define G_GROUPS 256
#define T_OUT 10
#define LF (L_LAYERS * F)   // 384

#define SCAN_BLOCKS ((N_NODES + 255) / 256)   // 196

// ---------------- scratch (device globals; no allocation allowed) ----------
__device__ __align__(16) __half g_agg_half[N_NODES * F];   // fp16, 12.8 MB
__device__ __align__(16) __half g_hc_half[N_NODES * LF];   // SOLE hc storage, 38.4 MB
__device__ __align__(16) __half g_x_half[N_NODES * F];     // fp16 mirror of x, 12.8 MB
__device__ __align__(16) __half g_wl_half[L_LAYERS * F * F];
__device__ __align__(16) __half g_wr_half[L_LAYERS * F * F];
__device__ __align__(16) int    g_deg[N_NODES];
__device__ __align__(16) int    g_row_start[N_NODES + 1];
__device__ __align__(16) int    g_cursor[N_NODES];
__device__ __align__(16) int    g_csr_src[N_EDGES];
__device__ __align__(16) int    g_bsum[SCAN_BLOCKS];

// ------- convert x & weights to fp16, zero deg, AND count degrees ----------
__global__ void convert_deg_kernel(const float* __restrict__ x,
                                   const float* __restrict__ Wl,
                                   const float* __restrict__ Wr,
                                   const int* __restrict__ ei) {
    int i = blockIdx.x * blockDim.x + threadIdx.x;
    if (i < N_NODES) g_deg[i] = 0;    // zero first...
    if (i < (N_NODES * F) / 4) {
        float4 v = reinterpret_cast<const float4*>(x)[i];
        __half2 h0 = __floats2half2_rn(v.x, v.y);
        __half2 h1 = __floats2half2_rn(v.z, v.w);
        uint2 packed;
        packed.x = *reinterpret_cast<uint32_t*>(&h0);
        packed.y = *reinterpret_cast<uint32_t*>(&h1);
        reinterpret_cast<uint2*>(g_x_half)[i] = packed;
    }
    if (i < (L_LAYERS * F * F) / 4) {
        float4 v = reinterpret_cast<const float4*>(Wl)[i];
        __half2 h0 = __floats2half2_rn(v.x, v.y);
        __half2 h1 = __floats2half2_rn(v.z, v.w);
        uint2 p;
        p.x = *reinterpret_cast<uint32_t*>(&h0);
        p.y = *reinterpret_cast<uint32_t*>(&h1);
        reinterpret_cast<uint2*>(g_wl_half)[i] = p;

        float4 w = reinterpret_cast<const float4*>(Wr)[i];
        __half2 g0 = __floats2half2_rn(w.x, w.y);
        __half2 g1 = __floats2half2_rn(w.z, w.w);
        uint2 q;
        q.x = *reinterpret_cast<uint32_t*>(&g0);
        q.y = *reinterpret_cast<uint32_t*>(&g1);
        reinterpret_cast<uint2*>(g_wr_half)[i] = q;
    }
}

__global__ void deg_kernel(const int* __restrict__ ei) {
    int e = blockIdx.x * blockDim.x + threadIdx.x;
    if (e < N_EDGES) {
        int d = ei[N_EDGES + e];
        if ((unsigned)d < N_NODES) atomicAdd(&g_deg[d], 1);
    }
}

// ---------------- CSR build -----------------------------------------------
__global__ void scan_reduce_kernel() {
    __shared__ int s[256];
    int tid = threadIdx.x;
    int idx = blockIdx.x * 256 + tid;
    s[tid] = (idx < N_NODES) ? g_deg[idx] : 0;
    __syncthreads();
#pragma unroll
    for (int off = 128; off > 0; off >>= 1) {
        if (tid < off) s[tid] += s[tid + off];
        __syncthreads();
    }
    if (tid == 0) g_bsum[blockIdx.x] = s[0];
}

__global__ void scan_final_kernel() {
    __shared__ int s[256];
    __shared__ int base_sh;
    int tid = threadIdx.x;

    int v2 = (tid < blockIdx.x) ? g_bsum[tid] : 0;
    s[tid] = v2;
    __syncthreads();
#pragma unroll
    for (int off = 128; off > 0; off >>= 1) {
        if (tid < off) s[tid] += s[tid + off];
        __syncthreads();
    }
    if (tid == 0) base_sh = s[0];
    __syncthreads();
    int base = base_sh;
    __syncthreads();   // s[] reused below

    int idx = blockIdx.x * 256 + tid;
    int v = (idx < N_NODES) ? g_deg[idx] : 0;
    s[tid] = v;
    __syncthreads();
#pragma unroll
    for (int off = 1; off < 256; off <<= 1) {
        int t = (tid >= off) ? s[tid - off] : 0;
        __syncthreads();
        s[tid] += t;
        __syncthreads();
    }
    if (idx < N_NODES) {
        int excl = base + s[tid] - v;
        g_row_start[idx] = excl;
        g_cursor[idx] = excl;
        if (idx == N_NODES - 1) g_row_start[N_NODES] = N_EDGES;
    }
}

__global__ void fill_kernel(const int* __restrict__ ei) {
    int e = blockIdx.x * blockDim.x + threadIdx.x;
    if (e < N_EDGES) {
        int src = ei[e];
        int dst = ei[N_EDGES + e];
        if ((unsigned)src < N_NODES && (unsigned)dst < N_NODES) {
            int pos = atomicAdd(&g_cursor[dst], 1);
            g_csr_src[pos] = src;
        }
    }
}

// ---------------- fp16 gather: agg[n] = mean_{s in N(n)} h[s] -------------
// 16 lanes per node (2 nodes/warp); lane owns a 16B (8-half) chunk of the row.
__global__ void __launch_bounds__(256) gather_kernel(int layer) {
    int gtid = blockIdx.x * blockDim.x + threadIdx.x;
    int node = gtid >> 4;
    int lane = gtid & 15;
    if (node >= N_NODES) return;

    const __half* h;
    int stride;   // in halves
    if (layer == 0) { h = g_x_half; stride = F; }
    else            { h = g_hc_half + (layer - 1) * F; stride = LF; }

    int start = g_row_start[node];
    int end   = g_row_start[node + 1];

    float acc[8];
#pragma unroll
    for (int j = 0; j < 8; ++j) acc[j] = 0.f;

    int i = start;
    for (; i + 4 <= end; i += 4) {
        int s0 = g_csr_src[i + 0];
        int s1 = g_csr_src[i + 1];
        int s2 = g_csr_src[i + 2];
        int s3 = g_csr_src[i + 3];
        uint4 u0 = *reinterpret_cast<const uint4*>(h + (size_t)s0 * stride + lane * 8);
        uint4 u1 = *reinterpret_cast<const uint4*>(h + (size_t)s1 * stride + lane * 8);
        uint4 u2 = *reinterpret_cast<const uint4*>(h + (size_t)s2 * stride + lane * 8);
        uint4 u3 = *reinterpret_cast<const uint4*>(h + (size_t)s3 * stride + lane * 8);
#pragma unroll
        for (int j = 0; j < 4; ++j) {
            uint4 u = (j == 0) ? u0 : (j == 1) ? u1 : (j == 2) ? u2 : u3;
            float2 f0 = __half22float2(*reinterpret_cast<__half2*>(&u.x));
            float2 f1 = __half22float2(*reinterpret_cast<__half2*>(&u.y));
            float2 f2 = __half22float2(*reinterpret_cast<__half2*>(&u.z));
            float2 f3 = __half22float2(*reinterpret_cast<__half2*>(&u.w));
            acc[0] += f0.x; acc[1] += f0.y; acc[2] += f1.x; acc[3] += f1.y;
            acc[4] += f2.x; acc[5] += f2.y; acc[6] += f3.x; acc[7] += f3.y;
        }
    }
    for (; i < end; ++i) {
        int s0 = g_csr_src[i];
        uint4 u = *reinterpret_cast<const uint4*>(h + (size_t)s0 * stride + lane * 8);
        float2 f0 = __half22float2(*reinterpret_cast<__half2*>(&u.x));
        float2 f1 = __half22float2(*reinterpret_cast<__half2*>(&u.y));
        float2 f2 = __half22float2(*reinterpret_cast<__half2*>(&u.z));
        float2 f3 = __half22float2(*reinterpret_cast<__half2*>(&u.w));
        acc[0] += f0.x; acc[1] += f0.y; acc[2] += f1.x; acc[3] += f1.y;
        acc[4] += f2.x; acc[5] += f2.y; acc[6] += f3.x; acc[7] += f3.y;
    }

    int d = end - start;
    float inv = d > 0 ? 1.0f / (float)d : 0.0f;
#pragma unroll
    for (int j = 0; j < 8; ++j) acc[j] *= inv;

    __half2 h0 = __floats2half2_rn(acc[0], acc[1]);
    __half2 h1 = __floats2half2_rn(acc[2], acc[3]);
    __half2 h2 = __floats2half2_rn(acc[4], acc[5]);
    __half2 h3 = __floats2half2_rn(acc[6], acc[7]);
    uint4 o;
    o.x = *reinterpret_cast<uint32_t*>(&h0);
    o.y = *reinterpret_cast<uint32_t*>(&h1);
    o.z = *reinterpret_cast<uint32_t*>(&h2);
    o.w = *reinterpret_cast<uint32_t*>(&h3);
    *reinterpret_cast<uint4*>(g_agg_half + (size_t)node * F + lane * 8) = o;
}

// ---------------- FP16 tensor-core GEMM, one pass per launch ---------------
// pass==1 (R): hc_l  = h @ Wr^T + bl          (write, runs on s2 || gather)
// pass==0 (L): hc_l += agg @ Wl^T             (RMW accumulate)
// mma.m16n8k16; block 128x128, 8 warps, warp tile 64x32; full K=128, 1 stage.
#define TSH 136                                 // halves per smem row (272B)
#define A_HALVES (128 * TSH)                    // 17408
#define GEMM_SMEM_BYTES (2 * A_HALVES * 2)      // 69632

__device__ __forceinline__ void mma_f16(float* d,
                                        const uint32_t* a, const uint32_t* b) {
    asm volatile(
        "mma.sync.aligned.m16n8k16.row.col.f32.f16.f16.f32 "
        "{%0,%1,%2,%3}, {%4,%5,%6,%7}, {%8,%9}, {%0,%1,%2,%3};\n"
        : "+f"(d[0]), "+f"(d[1]), "+f"(d[2]), "+f"(d[3])
        : "r"(a[0]), "r"(a[1]), "r"(a[2]), "r"(a[3]),
          "r"(b[0]), "r"(b[1]));
}

__global__ void __launch_bounds__(256, 2) sage_gemm_pass_kernel(
    int layer, int pass, const float* __restrict__ bl_all) {

    extern __shared__ __half smemh[];
    __half* As = smemh;              // [128][TSH]
    __half* Bs = smemh + A_HALVES;   // [128][TSH]

    const __half* hh;
    int strideH;   // in halves
    if (layer == 0) { hh = g_x_half; strideH = F; }
    else            { hh = g_hc_half + (layer - 1) * F; strideH = LF; }

    const __half* A_ptr = pass ? hh : g_agg_half;
    int strideA = pass ? strideH : F;
    const __half* Wh = pass ? (g_wr_half + layer * F * F)
                            : (g_wl_half + layer * F * F);

    int tid  = threadIdx.x;
    int warp = tid >> 5;
    int lane = tid & 31;
    int wm = warp >> 2;
    int wn = warp & 3;
    int grp = lane >> 2;
    int tg  = lane & 3;

    int row0 = blockIdx.x * 128;

    // ---- stage A and B (pure 16B copies) ----
#pragma unroll
    for (int i = 0; i < 8; ++i) {
        int t4 = tid + i * 256;          // 0..2047
        int m  = t4 >> 4;                // 0..127
        int c8 = (t4 & 15) * 8;          // 0..120 (halves)
        uint4 u = make_uint4(0, 0, 0, 0);
        int grow = row0 + m;
        if (grow < N_NODES)
            u = *reinterpret_cast<const uint4*>(A_ptr + (size_t)grow * strideA + c8);
        *reinterpret_cast<uint4*>(&As[m * TSH + c8]) = u;
    }
#pragma unroll
    for (int i = 0; i < 8; ++i) {
        int t4 = tid + i * 256;
        int j  = t4 >> 4;
        int c8 = (t4 & 15) * 8;
        uint4 u = *reinterpret_cast<const uint4*>(Wh + j * F + c8);
        *reinterpret_cast<uint4*>(&Bs[j * TSH + c8]) = u;
    }
    __syncthreads();

    float acc[4][4][4];
#pragma unroll
    for (int mf = 0; mf < 4; ++mf)
#pragma unroll
        for (int nf = 0; nf < 4; ++nf)
#pragma unroll
            for (int r = 0; r < 4; ++r) acc[mf][nf][r] = 0.f;

#pragma unroll
    for (int kk = 0; kk < F; kk += 16) {
        uint32_t afr[4][4], bfr[4][2];
#pragma unroll
        for (int mf = 0; mf < 4; ++mf) {
            int mr = wm * 64 + mf * 16 + grp;
            afr[mf][0] = *reinterpret_cast<const uint32_t*>(&As[mr * TSH + kk + 2 * tg]);
            afr[mf][1] = *reinterpret_cast<const uint32_t*>(&As[(mr + 8) * TSH + kk + 2 * tg]);
            afr[mf][2] = *reinterpret_cast<const uint32_t*>(&As[mr * TSH + kk + 2 * tg + 8]);
            afr[mf][3] = *reinterpret_cast<const uint32_t*>(&As[(mr + 8) * TSH + kk + 2 * tg + 8]);
        }
#pragma unroll
        for (int nf = 0; nf < 4; ++nf) {
            int nc = wn * 32 + nf * 8 + grp;
            bfr[nf][0] = *reinterpret_cast<const uint32_t*>(&Bs[nc * TSH + kk + 2 * tg]);
            bfr[nf][1] = *reinterpret_cast<const uint32_t*>(&Bs[nc * TSH + kk + 2 * tg + 8]);
        }
#pragma unroll
        for (int mf = 0; mf < 4; ++mf)
#pragma unroll
            for (int nf = 0; nf < 4; ++nf)
                mma_f16(acc[mf][nf], afr[mf], bfr[nf]);
    }

    // ---- epilogue ----
    const float* bias = bl_all + layer * F;
    __half* outh = g_hc_half + layer * F;
#pragma unroll
    for (int mf = 0; mf < 4; ++mf) {
        int r0 = row0 + wm * 64 + mf * 16 + grp;
        int r1 = r0 + 8;
#pragma unroll
        for (int nf = 0; nf < 4; ++nf) {
            int c = wn * 32 + nf * 8 + 2 * tg;
            if (pass) {   // R: write with bias
                float b0 = bias[c], b1 = bias[c + 1];
                if (r0 < N_NODES)
                    *reinterpret_cast<__half2*>(outh + (size_t)r0 * LF + c) =
                        __floats2half2_rn(acc[mf][nf][0] + b0, acc[mf][nf][1] + b1);
                if (r1 < N_NODES)
                    *reinterpret_cast<__half2*>(outh + (size_t)r1 * LF + c) =
                        __floats2half2_rn(acc[mf][nf][2] + b0, acc[mf][nf][3] + b1);
            } else {      // L: accumulate
                if (r0 < N_NODES) {
                    __half2* p = reinterpret_cast<__half2*>(outh + (size_t)r0 * LF + c);
                    float2 o = __half22float2(*p);
                    *p = __floats2half2_rn(o.x + acc[mf][nf][0], o.y + acc[mf][nf][1]);
                }
                if (r1 < N_NODES) {
                    __half2* p = reinterpret_cast<__half2*>(outh + (size_t)r1 * LF + c);
                    float2 o = __half22float2(*p);
                    *p = __floats2half2_rn(o.x + acc[mf][nf][2], o.y + acc[mf][nf][3]);
                }
            }
        }
    }
}

// ---------------- fused pool + MLP (fp16 hc input) -------------------------
__global__ void pool_mlp_kernel(const int* __restrict__ batch,
                                const float* __restrict__ W1, const float* __restrict__ b1,
                                const float* __restrict__ W2, const float* __restrict__ b2,
                                float* __restrict__ out) {
    int g = blockIdx.x;
    int tid = threadIdx.x;    // 0..383

    __shared__ __align__(16) float p[LF];
    __shared__ __align__(16) float z[F];

    int lo = 0, hi = N_NODES;
    while (lo < hi) { int mid = (lo + hi) >> 1; if (batch[mid] < g) lo = mid + 1; else hi = mid; }
    int start = lo;
    hi = N_NODES;
    while (lo < hi) { int mid = (lo + hi) >> 1; if (batch[mid] < g + 1) lo = mid + 1; else hi = mid; }
    int end = lo;

    float m = -FLT_MAX;
    for (int r = start; r < end; ++r)
        m = fmaxf(m, __half2float(g_hc_half[(size_t)r * LF + tid]));
    p[tid] = m;
    __syncthreads();

    if (tid < F) {
        float s = b1[tid];
        const float* w = W1 + tid * LF;
#pragma unroll 4
        for (int k = 0; k < LF; k += 4) {
            float4 wv = *reinterpret_cast<const float4*>(w + k);
            s += wv.x * p[k] + wv.y * p[k + 1] + wv.z * p[k + 2] + wv.w * p[k + 3];
        }
        z[tid] = fmaxf(s, 0.f);
    }
    __syncthreads();

    if (tid < T_OUT) {
        float o = b2[tid];
        const float* w2 = W2 + tid * F;
#pragma unroll 4
        for (int k = 0; k < F; k += 4) {
            float4 wv = *reinterpret_cast<const float4*>(w2 + k);
            o += wv.x * z[k] + wv.y * z[k + 1] + wv.z * z[k + 2] + wv.w * z[k + 3];
        }
        out[g * T_OUT + tid] = o;
    }
}

// ---------------- launch --------------------------------------------------
extern "C" void kernel_launch(void* const* d_in, const int* in_sizes, int n_in,
                              void* d_out, int out_size) {
    const float* x     = (const float*)d_in[0];
    const int*   ei    = (const int*)d_in[1];
    const int*   batch = (const int*)d_in[2];
    const float* Wl    = (const float*)d_in[3];
    const float* bl    = (const float*)d_in[4];
    const float* Wr    = (const float*)d_in[5];
    const float* W1    = (const float*)d_in[6];
    const float* b1    = (const float*)d_in[7];
    const float* W2    = (const float*)d_in[8];
    const float* b2    = (const float*)d_in[9];
    float* out = (float*)d_out;

    static cudaStream_t s2 = nullptr;
    static cudaEvent_t ev_fork[L_LAYERS];
    static cudaEvent_t ev_done[L_LAYERS];
    static bool init_done = false;
    if (!init_done) {
        cudaFuncSetAttribute(sage_gemm_pass_kernel,
                             cudaFuncAttributeMaxDynamicSharedMemorySize,
                             GEMM_SMEM_BYTES);
        cudaStreamCreateWithFlags(&s2, cudaStreamNonBlocking);
        for (int i = 0; i < L_LAYERS; ++i) {
            cudaEventCreateWithFlags(&ev_fork[i], cudaEventDisableTiming);
            cudaEventCreateWithFlags(&ev_done[i], cudaEventDisableTiming);
        }
        init_done = true;
    }

    // fp16 convert (x + weights) + CSR build
    convert_deg_kernel<<<(N_NODES * F / 4 + 255) / 256, 256>>>(x, Wl, Wr, ei);
    deg_kernel<<<(N_EDGES + 255) / 256, 256>>>(ei);
    scan_reduce_kernel<<<SCAN_BLOCKS, 256>>>();
    scan_final_kernel<<<SCAN_BLOCKS, 256>>>();
    fill_kernel<<<(N_EDGES + 255) / 256, 256>>>(ei);

    const int gather_blocks = (N_NODES * 16 + 255) / 256;  // 3125
    const int gemm_blocks   = (N_NODES + 127) / 128;       // 391

    for (int layer = 0; layer < L_LAYERS; ++layer) {
        // fork: R-pass (h @ Wr^T + bl) on s2, concurrent with gather on main
        cudaEventRecord(ev_fork[layer], 0);
        cudaStreamWaitEvent(s2, ev_fork[layer], 0);
        sage_gemm_pass_kernel<<<gemm_blocks, 256, GEMM_SMEM_BYTES, s2>>>(layer, 1, bl);
        cudaEventRecord(ev_done[layer], s2);

        gather_kernel<<<gather_blocks, 256>>>(layer);

        // join, then L-pass accumulate (agg @ Wl^T)
        cudaStreamWaitEvent(0, ev_done[layer], 0);
        sage_gemm_pass_kernel<<<gemm_blocks, 256, GEMM_SMEM_BYTES>>>(layer, 0, bl);
    }

    pool_mlp_kernel<<<G_GROUPS, LF>>>(batch, W1, b1, W2, b2, out);
}

// round 17
// speedup vs baseline: 1.2910x; 1.2910x over previous
#include <cuda_runtime.h>
#include <cuda_fp16.h>
#include <float.h>
#include <stdint.h>

#define N_NODES 50000
#define N_EDGES 800000
#define F 128
#define L_LAYERS 3
#define G_GROUPS 256
#define T_OUT 10
#define LF (L_LAYERS * F)   // 384

#define SCAN_BLOCKS ((N_NODES + 255) / 256)   // 196

// ---------------- scratch (device globals; no allocation allowed) ----------
__device__ __align__(16) __half g_agg_half[N_NODES * F];   // fp16, 12.8 MB
__device__ __align__(16) __half g_hc_half[N_NODES * LF];   // SOLE hc storage, 38.4 MB
__device__ __align__(16) __half g_x_half[N_NODES * F];     // fp16 mirror of x, 12.8 MB
__device__ __align__(16) __half g_wl_half[L_LAYERS * F * F];
__device__ __align__(16) __half g_wr_half[L_LAYERS * F * F];
__device__ __align__(16) int    g_deg[N_NODES];
__device__ __align__(16) int    g_row_start[N_NODES + 1];
__device__ __align__(16) int    g_cursor[N_NODES];
__device__ __align__(16) int    g_csr_src[N_EDGES];
__device__ __align__(16) int    g_bsum[SCAN_BLOCKS];

// ---------------- convert x & weights to fp16, zero deg --------------------
__global__ void convert_kernel(const float* __restrict__ x,
                               const float* __restrict__ Wl,
                               const float* __restrict__ Wr) {
    int i = blockIdx.x * blockDim.x + threadIdx.x;
    if (i < (N_NODES * F) / 4) {
        float4 v = reinterpret_cast<const float4*>(x)[i];
        __half2 h0 = __floats2half2_rn(v.x, v.y);
        __half2 h1 = __floats2half2_rn(v.z, v.w);
        uint2 packed;
        packed.x = *reinterpret_cast<uint32_t*>(&h0);
        packed.y = *reinterpret_cast<uint32_t*>(&h1);
        reinterpret_cast<uint2*>(g_x_half)[i] = packed;
    }
    if (i < (L_LAYERS * F * F) / 4) {
        float4 v = reinterpret_cast<const float4*>(Wl)[i];
        __half2 h0 = __floats2half2_rn(v.x, v.y);
        __half2 h1 = __floats2half2_rn(v.z, v.w);
        uint2 p;
        p.x = *reinterpret_cast<uint32_t*>(&h0);
        p.y = *reinterpret_cast<uint32_t*>(&h1);
        reinterpret_cast<uint2*>(g_wl_half)[i] = p;

        float4 w = reinterpret_cast<const float4*>(Wr)[i];
        __half2 g0 = __floats2half2_rn(w.x, w.y);
        __half2 g1 = __floats2half2_rn(w.z, w.w);
        uint2 q;
        q.x = *reinterpret_cast<uint32_t*>(&g0);
        q.y = *reinterpret_cast<uint32_t*>(&g1);
        reinterpret_cast<uint2*>(g_wr_half)[i] = q;
    }
    if (i < N_NODES) g_deg[i] = 0;
}

// ---------------- CSR build (4 edges per thread) ---------------------------
__global__ void deg_kernel(const int* __restrict__ ei) {
    int e4 = blockIdx.x * blockDim.x + threadIdx.x;   // 0 .. E/4-1
    if (e4 < N_EDGES / 4) {
        int4 d = reinterpret_cast<const int4*>(ei + N_EDGES)[e4];
        atomicAdd(&g_deg[d.x], 1);
        atomicAdd(&g_deg[d.y], 1);
        atomicAdd(&g_deg[d.z], 1);
        atomicAdd(&g_deg[d.w], 1);
    }
}

__global__ void scan_reduce_kernel() {
    __shared__ int s[256];
    int tid = threadIdx.x;
    int idx = blockIdx.x * 256 + tid;
    s[tid] = (idx < N_NODES) ? g_deg[idx] : 0;
    __syncthreads();
#pragma unroll
    for (int off = 128; off > 0; off >>= 1) {
        if (tid < off) s[tid] += s[tid + off];
        __syncthreads();
    }
    if (tid == 0) g_bsum[blockIdx.x] = s[0];
}

__global__ void scan_final_kernel() {
    __shared__ int s[256];
    __shared__ int base_sh;
    int tid = threadIdx.x;

    int v2 = (tid < blockIdx.x) ? g_bsum[tid] : 0;
    s[tid] = v2;
    __syncthreads();
#pragma unroll
    for (int off = 128; off > 0; off >>= 1) {
        if (tid < off) s[tid] += s[tid + off];
        __syncthreads();
    }
    if (tid == 0) base_sh = s[0];
    __syncthreads();
    int base = base_sh;
    __syncthreads();   // s[] reused below

    int idx = blockIdx.x * 256 + tid;
    int v = (idx < N_NODES) ? g_deg[idx] : 0;
    s[tid] = v;
    __syncthreads();
#pragma unroll
    for (int off = 1; off < 256; off <<= 1) {
        int t = (tid >= off) ? s[tid - off] : 0;
        __syncthreads();
        s[tid] += t;
        __syncthreads();
    }
    if (idx < N_NODES) {
        int excl = base + s[tid] - v;
        g_row_start[idx] = excl;
        g_cursor[idx] = excl;
        if (idx == N_NODES - 1) g_row_start[N_NODES] = N_EDGES;
    }
}

__global__ void fill_kernel(const int* __restrict__ ei) {
    int e4 = blockIdx.x * blockDim.x + threadIdx.x;
    if (e4 < N_EDGES / 4) {
        int4 s = reinterpret_cast<const int4*>(ei)[e4];
        int4 d = reinterpret_cast<const int4*>(ei + N_EDGES)[e4];
        g_csr_src[atomicAdd(&g_cursor[d.x], 1)] = s.x;
        g_csr_src[atomicAdd(&g_cursor[d.y], 1)] = s.y;
        g_csr_src[atomicAdd(&g_cursor[d.z], 1)] = s.z;
        g_csr_src[atomicAdd(&g_cursor[d.w], 1)] = s.w;
    }
}

// ---------------- fp16 gather: agg[n] = mean_{s in N(n)} h[s] -------------
// 16 lanes per node (2 nodes/warp); lane owns a 16B (8-half) chunk of the row.
// Accumulation fp32; agg written fp16.
__global__ void __launch_bounds__(256) gather_kernel(int layer) {
    int gtid = blockIdx.x * blockDim.x + threadIdx.x;
    int node = gtid >> 4;
    int lane = gtid & 15;
    if (node >= N_NODES) return;

    const __half* h;
    int stride;   // in halves
    if (layer == 0) { h = g_x_half; stride = F; }
    else            { h = g_hc_half + (layer - 1) * F; stride = LF; }

    int start = g_row_start[node];
    int end   = g_row_start[node + 1];

    float acc[8];
#pragma unroll
    for (int j = 0; j < 8; ++j) acc[j] = 0.f;

    int i = start;
    for (; i + 4 <= end; i += 4) {
        int s0 = g_csr_src[i + 0];
        int s1 = g_csr_src[i + 1];
        int s2 = g_csr_src[i + 2];
        int s3 = g_csr_src[i + 3];
        uint4 u0 = *reinterpret_cast<const uint4*>(h + (size_t)s0 * stride + lane * 8);
        uint4 u1 = *reinterpret_cast<const uint4*>(h + (size_t)s1 * stride + lane * 8);
        uint4 u2 = *reinterpret_cast<const uint4*>(h + (size_t)s2 * stride + lane * 8);
        uint4 u3 = *reinterpret_cast<const uint4*>(h + (size_t)s3 * stride + lane * 8);
#pragma unroll
        for (int j = 0; j < 4; ++j) {
            uint4 u = (j == 0) ? u0 : (j == 1) ? u1 : (j == 2) ? u2 : u3;
            float2 f0 = __half22float2(*reinterpret_cast<__half2*>(&u.x));
            float2 f1 = __half22float2(*reinterpret_cast<__half2*>(&u.y));
            float2 f2 = __half22float2(*reinterpret_cast<__half2*>(&u.z));
            float2 f3 = __half22float2(*reinterpret_cast<__half2*>(&u.w));
            acc[0] += f0.x; acc[1] += f0.y; acc[2] += f1.x; acc[3] += f1.y;
            acc[4] += f2.x; acc[5] += f2.y; acc[6] += f3.x; acc[7] += f3.y;
        }
    }
    for (; i < end; ++i) {
        int s0 = g_csr_src[i];
        uint4 u = *reinterpret_cast<const uint4*>(h + (size_t)s0 * stride + lane * 8);
        float2 f0 = __half22float2(*reinterpret_cast<__half2*>(&u.x));
        float2 f1 = __half22float2(*reinterpret_cast<__half2*>(&u.y));
        float2 f2 = __half22float2(*reinterpret_cast<__half2*>(&u.z));
        float2 f3 = __half22float2(*reinterpret_cast<__half2*>(&u.w));
        acc[0] += f0.x; acc[1] += f0.y; acc[2] += f1.x; acc[3] += f1.y;
        acc[4] += f2.x; acc[5] += f2.y; acc[6] += f3.x; acc[7] += f3.y;
    }

    int d = end - start;
    float inv = d > 0 ? 1.0f / (float)d : 0.0f;
#pragma unroll
    for (int j = 0; j < 8; ++j) acc[j] *= inv;

    __half2 h0 = __floats2half2_rn(acc[0], acc[1]);
    __half2 h1 = __floats2half2_rn(acc[2], acc[3]);
    __half2 h2 = __floats2half2_rn(acc[4], acc[5]);
    __half2 h3 = __floats2half2_rn(acc[6], acc[7]);
    uint4 o;
    o.x = *reinterpret_cast<uint32_t*>(&h0);
    o.y = *reinterpret_cast<uint32_t*>(&h1);
    o.z = *reinterpret_cast<uint32_t*>(&h2);
    o.w = *reinterpret_cast<uint32_t*>(&h3);
    *reinterpret_cast<uint4*>(g_agg_half + (size_t)node * F + lane * 8) = o;
}

// ---------------- FP16 tensor-core fused SAGE GEMM (R14 shape) -------------
// out[n,:] = agg[n,:] @ Wl^T + h[n,:] @ Wr^T + bl
// mma.m16n8k16.f32.f16.f16.f32; block 128x128, 8 warps, warp tile 64x32.
// Whole K=128 staged per pass; ALL staging is pure 16B copies.
// Frag loads: word bank = 4*row + tg (stride 68 words) -> conflict-free.
#define TSH 136                                 // halves per smem row (272B)
#define A_HALVES (128 * TSH)                    // 17408
#define GEMM_SMEM_BYTES (2 * A_HALVES * 2)      // 69632

__device__ __forceinline__ void mma_f16(float* d,
                                        const uint32_t* a, const uint32_t* b) {
    asm volatile(
        "mma.sync.aligned.m16n8k16.row.col.f32.f16.f16.f32 "
        "{%0,%1,%2,%3}, {%4,%5,%6,%7}, {%8,%9}, {%0,%1,%2,%3};\n"
        : "+f"(d[0]), "+f"(d[1]), "+f"(d[2]), "+f"(d[3])
        : "r"(a[0]), "r"(a[1]), "r"(a[2]), "r"(a[3]),
          "r"(b[0]), "r"(b[1]));
}

__global__ void __launch_bounds__(256, 2) sage_gemm_f16_kernel(
    int layer, const float* __restrict__ bl_all) {

    extern __shared__ __half smemh[];
    __half* As = smemh;              // [128][TSH]
    __half* Bs = smemh + A_HALVES;   // [128][TSH]

    const __half* hh;
    int strideH;   // in halves
    if (layer == 0) { hh = g_x_half; strideH = F; }
    else            { hh = g_hc_half + (layer - 1) * F; strideH = LF; }

    int tid  = threadIdx.x;
    int warp = tid >> 5;
    int lane = tid & 31;
    int wm = warp >> 2;
    int wn = warp & 3;
    int grp = lane >> 2;
    int tg  = lane & 3;

    int row0 = blockIdx.x * 128;

    float acc[4][4][4];
#pragma unroll
    for (int mf = 0; mf < 4; ++mf)
#pragma unroll
        for (int nf = 0; nf < 4; ++nf)
#pragma unroll
            for (int r = 0; r < 4; ++r) acc[mf][nf][r] = 0.f;

    for (int pass = 0; pass < 2; ++pass) {
        const __half* A_ptr = pass ? hh : g_agg_half;
        int strideA = pass ? strideH : F;
        const __half* Wh = pass ? (g_wr_half + layer * F * F)
                                : (g_wl_half + layer * F * F);

        __syncthreads();   // protect previous stage's frag reads
        // ---- A stage: pure 16B copies (2048 slots of 8 halves) ----
#pragma unroll
        for (int i = 0; i < 8; ++i) {
            int t4 = tid + i * 256;          // 0..2047
            int m  = t4 >> 4;                // 0..127
            int c8 = (t4 & 15) * 8;          // 0..120 (halves)
            uint4 u = make_uint4(0, 0, 0, 0);
            int grow = row0 + m;
            if (grow < N_NODES)
                u = *reinterpret_cast<const uint4*>(A_ptr + (size_t)grow * strideA + c8);
            *reinterpret_cast<uint4*>(&As[m * TSH + c8]) = u;
        }
        // ---- B stage: pure 16B copies ----
#pragma unroll
        for (int i = 0; i < 8; ++i) {
            int t4 = tid + i * 256;
            int j  = t4 >> 4;
            int c8 = (t4 & 15) * 8;
            uint4 u = *reinterpret_cast<const uint4*>(Wh + j * F + c8);
            *reinterpret_cast<uint4*>(&Bs[j * TSH + c8]) = u;
        }
        __syncthreads();

#pragma unroll
        for (int kk = 0; kk < F; kk += 16) {
            uint32_t afr[4][4], bfr[4][2];
#pragma unroll
            for (int mf = 0; mf < 4; ++mf) {
                int mr = wm * 64 + mf * 16 + grp;
                afr[mf][0] = *reinterpret_cast<const uint32_t*>(&As[mr * TSH + kk + 2 * tg]);
                afr[mf][1] = *reinterpret_cast<const uint32_t*>(&As[(mr + 8) * TSH + kk + 2 * tg]);
                afr[mf][2] = *reinterpret_cast<const uint32_t*>(&As[mr * TSH + kk + 2 * tg + 8]);
                afr[mf][3] = *reinterpret_cast<const uint32_t*>(&As[(mr + 8) * TSH + kk + 2 * tg + 8]);
            }
#pragma unroll
            for (int nf = 0; nf < 4; ++nf) {
                int nc = wn * 32 + nf * 8 + grp;
                bfr[nf][0] = *reinterpret_cast<const uint32_t*>(&Bs[nc * TSH + kk + 2 * tg]);
                bfr[nf][1] = *reinterpret_cast<const uint32_t*>(&Bs[nc * TSH + kk + 2 * tg + 8]);
            }
#pragma unroll
            for (int mf = 0; mf < 4; ++mf)
#pragma unroll
                for (int nf = 0; nf < 4; ++nf)
                    mma_f16(acc[mf][nf], afr[mf], bfr[nf]);
        }
    }

    // ---- epilogue: + bias, write fp16 hc slice ----
    const float* bias = bl_all + layer * F;
    __half* outh = g_hc_half + layer * F;
#pragma unroll
    for (int mf = 0; mf < 4; ++mf) {
        int r0 = row0 + wm * 64 + mf * 16 + grp;
        int r1 = r0 + 8;
#pragma unroll
        for (int nf = 0; nf < 4; ++nf) {
            int c = wn * 32 + nf * 8 + 2 * tg;
            float b0 = bias[c], b1 = bias[c + 1];
            if (r0 < N_NODES)
                *reinterpret_cast<__half2*>(outh + (size_t)r0 * LF + c) =
                    __floats2half2_rn(acc[mf][nf][0] + b0, acc[mf][nf][1] + b1);
            if (r1 < N_NODES)
                *reinterpret_cast<__half2*>(outh + (size_t)r1 * LF + c) =
                    __floats2half2_rn(acc[mf][nf][2] + b0, acc[mf][nf][3] + b1);
        }
    }
}

// ---------------- fused pool + MLP (fp16 hc input) -------------------------
__global__ void pool_mlp_kernel(const int* __restrict__ batch,
                                const float* __restrict__ W1, const float* __restrict__ b1,
                                const float* __restrict__ W2, const float* __restrict__ b2,
                                float* __restrict__ out) {
    int g = blockIdx.x;
    int tid = threadIdx.x;    // 0..383

    __shared__ __align__(16) float p[LF];
    __shared__ __align__(16) float z[F];

    int lo = 0, hi = N_NODES;
    while (lo < hi) { int mid = (lo + hi) >> 1; if (batch[mid] < g) lo = mid + 1; else hi = mid; }
    int start = lo;
    hi = N_NODES;
    while (lo < hi) { int mid = (lo + hi) >> 1; if (batch[mid] < g + 1) lo = mid + 1; else hi = mid; }
    int end = lo;

    float m = -FLT_MAX;
    for (int r = start; r < end; ++r)
        m = fmaxf(m, __half2float(g_hc_half[(size_t)r * LF + tid]));
    p[tid] = m;
    __syncthreads();

    if (tid < F) {
        float s = b1[tid];
        const float* w = W1 + tid * LF;
#pragma unroll 4
        for (int k = 0; k < LF; k += 4) {
            float4 wv = *reinterpret_cast<const float4*>(w + k);
            s += wv.x * p[k] + wv.y * p[k + 1] + wv.z * p[k + 2] + wv.w * p[k + 3];
        }
        z[tid] = fmaxf(s, 0.f);
    }
    __syncthreads();

    if (tid < T_OUT) {
        float o = b2[tid];
        const float* w2 = W2 + tid * F;
#pragma unroll 4
        for (int k = 0; k < F; k += 4) {
            float4 wv = *reinterpret_cast<const float4*>(w2 + k);
            o += wv.x * z[k] + wv.y * z[k + 1] + wv.z * z[k + 2] + wv.w * z[k + 3];
        }
        out[g * T_OUT + tid] = o;
    }
}

// ---------------- launch --------------------------------------------------
extern "C" void kernel_launch(void* const* d_in, const int* in_sizes, int n_in,
                              void* d_out, int out_size) {
    const float* x     = (const float*)d_in[0];
    const int*   ei    = (const int*)d_in[1];
    const int*   batch = (const int*)d_in[2];
    const float* Wl    = (const float*)d_in[3];
    const float* bl    = (const float*)d_in[4];
    const float* Wr    = (const float*)d_in[5];
    const float* W1    = (const float*)d_in[6];
    const float* b1    = (const float*)d_in[7];
    const float* W2    = (const float*)d_in[8];
    const float* b2    = (const float*)d_in[9];
    float* out = (float*)d_out;

    static bool init_done = false;
    if (!init_done) {
        cudaFuncSetAttribute(sage_gemm_f16_kernel,
                             cudaFuncAttributeMaxDynamicSharedMemorySize,
                             GEMM_SMEM_BYTES);
        init_done = true;
    }

    // fp16 convert (x + weights) + CSR build
    convert_kernel<<<(N_NODES * F / 4 + 255) / 256, 256>>>(x, Wl, Wr);
    deg_kernel<<<(N_EDGES / 4 + 255) / 256, 256>>>(ei);
    scan_reduce_kernel<<<SCAN_BLOCKS, 256>>>();
    scan_final_kernel<<<SCAN_BLOCKS, 256>>>();
    fill_kernel<<<(N_EDGES / 4 + 255) / 256, 256>>>(ei);

    const int gather_blocks = (N_NODES * 16 + 255) / 256;  // 3125
    const int gemm_blocks   = (N_NODES + 127) / 128;       // 391

    for (int layer = 0; layer < L_LAYERS; ++layer) {
        gather_kernel<<<gather_blocks, 256>>>(layer);
        sage_gemm_f16_kernel<<<gemm_blocks, 256, GEMM_SMEM_BYTES>>>(layer, bl);
    }

    pool_mlp_kernel<<<G_GROUPS, LF>>>(batch, W1, b1, W2, b2, out);
}